// round 14
// baseline (speedup 1.0000x reference)
#include <cuda_runtime.h>

// ---------------------------------------------------------------------------
// GCN 3-layer: (GCNConv -> BN -> ReLU) x2 -> GCNConv.  N=100k, E=1.2M, D=64.
//
// R11 changes vs R10 (321.8us):
//  - 12 launches (was 18): init fuses zero+detect; single decoupled-lookback
//    scan kernel (includes dinv + rowoff[n]); BN stats fused into gather.
//  - dinv pre-scaled into GEMM epilogue -> gather has NO per-edge dinv load.
//  - gather: half-warp per node, float4 (LDG.128), 2 accumulators.
//  - GEMM retiled 8 rows x 8 cols per thread (less smem traffic), FFMA2.
// ---------------------------------------------------------------------------

#define NMAX 100000
#define EMAX 1200000
#define BN_EPS 1e-5f
#define GBLK 1024          // gather grid
#define SCAN_ITEMS 2048
#define GEMM_SMEM ((128 * 65 + 64 * 64) * 4)

__device__ float g_bufA[NMAX * 64];
__device__ float g_bufB[NMAX * 64];
__device__ int   g_cnt[NMAX];
__device__ int   g_cursor[NMAX];
__device__ int   g_rowoff[NMAX + 1];
__device__ float g_dinv[NMAX];
__device__ int   g_csr[EMAX];
__device__ int   g_bagg[64];
__device__ int   g_bpref[64];
__device__ volatile int g_bflag[64];   // 0 none, 1 aggregate, 2 prefix
__device__ float g_pS[GBLK * 64];
__device__ float g_pQ[GBLK * 64];
__device__ float g_bnA[64];
__device__ float g_bnB[64];
__device__ int   g_is64;

// ---- packed fp32x2 FFMA2 (bit-exact vs 2x FFMA) -----------------------------
__device__ __forceinline__ unsigned long long pack2(float lo, float hi) {
    unsigned long long r;
    asm("mov.b64 %0, {%1, %2};" : "=l"(r) : "f"(lo), "f"(hi));
    return r;
}
__device__ __forceinline__ void unpack2(unsigned long long v, float& lo, float& hi) {
    asm("mov.b64 {%0, %1}, %2;" : "=f"(lo), "=f"(hi) : "l"(v));
}
__device__ __forceinline__ unsigned long long fma2(unsigned long long a,
                                                   unsigned long long b,
                                                   unsigned long long c) {
    unsigned long long d;
    asm("fma.rn.f32x2 %0, %1, %2, %3;" : "=l"(d) : "l"(a), "l"(b), "l"(c));
    return d;
}

__device__ __forceinline__ int edge_val(const void* ei, long long idx) {
    if (g_is64) return (int)((const long long*)ei)[idx];
    return ((const int*)ei)[idx];
}

// ---- init: zero counters/flags + detect int64-vs-int32 edge layout ----------
__global__ void k_init(const unsigned int* p, int E, int n) {
    int gid = blockIdx.x * blockDim.x + threadIdx.x;
    int stride = gridDim.x * blockDim.x;
    for (int i = gid; i < n; i += stride) { g_cnt[i] = 0; g_cursor[i] = 0; }
    if (gid < 64) g_bflag[gid] = 0;
    if (blockIdx.x == 0) {
        __shared__ int any;
        if (threadIdx.x == 0) any = 0;
        __syncthreads();
        int samples = E < 4096 ? E : 4096;
        for (int i = threadIdx.x; i < samples; i += blockDim.x)
            if (p[2 * i + 1] != 0u) any = 1;   // nonzero hi-word => int32 layout
        __syncthreads();
        if (threadIdx.x == 0) g_is64 = any ? 0 : 1;
    }
}

__global__ void k_hist(const void* ei, int E) {
    int e = blockIdx.x * blockDim.x + threadIdx.x;
    if (e >= E) return;
    int d = edge_val(ei, (long long)E + e);
    atomicAdd(&g_cnt[d], 1);
}

// ---- single-kernel exclusive scan (decoupled lookback) + dinv ---------------
__global__ void __launch_bounds__(256) k_scan(int n, int nb) {
    __shared__ int wsum[8], woff[8];
    __shared__ int s_excl;
    int tid = threadIdx.x, b = blockIdx.x;
    int base = b * SCAN_ITEMS + tid * 8;
    int v[8];
    int tsum = 0;
#pragma unroll
    for (int i = 0; i < 8; i++) {
        v[i] = (base + i < n) ? g_cnt[base + i] : 0;
        tsum += v[i];
    }
    int lane = tid & 31, wid = tid >> 5;
    int inc = tsum;
#pragma unroll
    for (int off = 1; off < 32; off <<= 1) {
        int t = __shfl_up_sync(0xffffffffu, inc, off);
        if (lane >= off) inc += t;
    }
    if (lane == 31) wsum[wid] = inc;
    __syncthreads();
    if (tid == 0) {
        int acc = 0;
#pragma unroll
        for (int w = 0; w < 8; w++) { woff[w] = acc; acc += wsum[w]; }
        int excl = 0;
        if (b == 0) {
            *(volatile int*)&g_bpref[0] = acc;
            __threadfence();
            g_bflag[0] = 2;
        } else {
            *(volatile int*)&g_bagg[b] = acc;
            __threadfence();
            g_bflag[b] = 1;
            int p = b - 1;
            while (true) {
                int f;
                do { f = g_bflag[p]; } while (f == 0);
                __threadfence();
                if (f == 2) { excl += *(volatile int*)&g_bpref[p]; break; }
                excl += *(volatile int*)&g_bagg[p];
                p--;
            }
            *(volatile int*)&g_bpref[b] = excl + acc;
            __threadfence();
            g_bflag[b] = 2;
        }
        s_excl = excl;
        if (b == nb - 1) g_rowoff[n] = excl + acc;
    }
    __syncthreads();
    int run = s_excl + woff[wid] + (inc - tsum);
#pragma unroll
    for (int i = 0; i < 8; i++) {
        int idx = base + i;
        if (idx < n) {
            g_rowoff[idx] = run;
            g_dinv[idx] = rsqrtf((float)(v[i] + 1));
        }
        run += v[i];
    }
}

__global__ void k_fill(const void* ei, int E) {
    int e = blockIdx.x * blockDim.x + threadIdx.x;
    if (e >= E) return;
    int s = edge_val(ei, e);
    int d = edge_val(ei, (long long)E + e);
    int pos = g_rowoff[d] + atomicAdd(&g_cursor[d], 1);
    g_csr[pos] = s;
}

// ---- fused (BN+ReLU) + GEMM + dinv row-scale --------------------------------
// Hs[r,:] = dinv[r] * ( act(X[r,:]) @ W ).  128 rows/block, 8r x 8c per thread.
__global__ void __launch_bounds__(128)
k_gemm(const float* __restrict__ X, const float* __restrict__ W,
       int use_bn, float* __restrict__ H, int n) {
    extern __shared__ float sm[];
    float (*Xs)[65] = (float(*)[65])sm;   // 128 x 65
    float* Ws = sm + 128 * 65;            // 64 x 64

    int tid = threadIdx.x;
    int rowBase = blockIdx.x * 128;

    for (int i = tid; i < 64 * 64; i += 128) Ws[i] = W[i];
    for (int i = tid; i < 128 * 64; i += 128) {
        int r = i >> 6, c = i & 63;
        int gr = rowBase + r;
        float v = 0.f;
        if (gr < n) {
            v = X[gr * 64 + c];
            if (use_bn) v = fmaxf(fmaf(v, g_bnA[c], g_bnB[c]), 0.f);
        }
        Xs[r][c] = v;
    }
    __syncthreads();

    int rgrp = tid >> 3;          // 0..15 -> 8 rows each
    int cq = tid & 7;             // 0..7  -> 8 cols each
    int r0 = rgrp * 8;

    unsigned long long acc[8][4];
#pragma unroll
    for (int i = 0; i < 8; i++)
#pragma unroll
        for (int j = 0; j < 4; j++) acc[i][j] = 0ULL;

#pragma unroll 4
    for (int k = 0; k < 64; k++) {
        unsigned long long xx[8];
#pragma unroll
        for (int i = 0; i < 8; i++) {
            float xv = Xs[r0 + i][k];
            xx[i] = pack2(xv, xv);
        }
        const float4* Wrow = (const float4*)(Ws + k * 64);
        float4 wa = Wrow[cq * 2 + 0];
        float4 wb = Wrow[cq * 2 + 1];
        unsigned long long wv[4] = {pack2(wa.x, wa.y), pack2(wa.z, wa.w),
                                    pack2(wb.x, wb.y), pack2(wb.z, wb.w)};
#pragma unroll
        for (int i = 0; i < 8; i++)
#pragma unroll
            for (int j = 0; j < 4; j++)
                acc[i][j] = fma2(xx[i], wv[j], acc[i][j]);
    }

#pragma unroll
    for (int i = 0; i < 8; i++) {
        int gr = rowBase + r0 + i;
        if (gr < n) {
            float dv = g_dinv[gr];
            float a0, a1, a2, a3, a4, a5, a6, a7;
            unpack2(acc[i][0], a0, a1);
            unpack2(acc[i][1], a2, a3);
            unpack2(acc[i][2], a4, a5);
            unpack2(acc[i][3], a6, a7);
            float4* dst = (float4*)(H + gr * 64 + cq * 8);
            dst[0] = make_float4(a0 * dv, a1 * dv, a2 * dv, a3 * dv);
            dst[1] = make_float4(a4 * dv, a5 * dv, a6 * dv, a7 * dv);
        }
    }
}

// ---- aggregation + fused BN partial stats -----------------------------------
// out[n,:] = b + dinv[n]*( sum_{e:dst=n} Hs[src] + Hs[n] )   (Hs pre-scaled)
// Half-warp (16 lanes x float4) per node, grid-stride.
__device__ __forceinline__ float4 f4add(float4 a, float4 b) {
    return make_float4(a.x + b.x, a.y + b.y, a.z + b.z, a.w + b.w);
}

__global__ void __launch_bounds__(256)
k_gather(const float4* __restrict__ Hs, const float* __restrict__ bias,
         float4* __restrict__ out, int n, int do_stats) {
    __shared__ float sS[16][64];
    __shared__ float sQ[16][64];
    int tid = threadIdx.x;
    int l = tid & 15;             // lane within half-warp -> channels 4l..4l+3
    int hw = tid >> 4;            // half-warp id in block (0..15)
    int ghw = blockIdx.x * 16 + hw;
    int stride = gridDim.x * 16;

    float4 b4 = ((const float4*)bias)[l];
    float4 S = make_float4(0.f, 0.f, 0.f, 0.f);
    float4 Q = make_float4(0.f, 0.f, 0.f, 0.f);

    for (int node = ghw; node < n; node += stride) {
        int beg = g_rowoff[node];
        int end = g_rowoff[node + 1];
        float dn = g_dinv[node];
        float4 a0 = Hs[(long long)node * 16 + l];   // self term (pre-scaled)
        float4 a1 = make_float4(0.f, 0.f, 0.f, 0.f);
        int j = beg;
        for (; j + 4 <= end; j += 4) {
            int s0 = g_csr[j + 0], s1 = g_csr[j + 1];
            int s2 = g_csr[j + 2], s3 = g_csr[j + 3];
            float4 v0 = Hs[(long long)s0 * 16 + l];
            float4 v1 = Hs[(long long)s1 * 16 + l];
            float4 v2 = Hs[(long long)s2 * 16 + l];
            float4 v3 = Hs[(long long)s3 * 16 + l];
            a0 = f4add(a0, v0);
            a1 = f4add(a1, v1);
            a0 = f4add(a0, v2);
            a1 = f4add(a1, v3);
        }
        for (; j < end; j++) {
            int s = g_csr[j];
            a0 = f4add(a0, Hs[(long long)s * 16 + l]);
        }
        float4 t = f4add(a0, a1);
        float4 o = make_float4(fmaf(dn, t.x, b4.x), fmaf(dn, t.y, b4.y),
                               fmaf(dn, t.z, b4.z), fmaf(dn, t.w, b4.w));
        out[(long long)node * 16 + l] = o;
        if (do_stats) {
            S = f4add(S, o);
            Q.x = fmaf(o.x, o.x, Q.x); Q.y = fmaf(o.y, o.y, Q.y);
            Q.z = fmaf(o.z, o.z, Q.z); Q.w = fmaf(o.w, o.w, Q.w);
        }
    }

    if (do_stats) {
        ((float4*)&sS[hw][l * 4])[0] = S;
        ((float4*)&sQ[hw][l * 4])[0] = Q;
        __syncthreads();
        if (tid < 64) {
            float s = 0.f, q = 0.f;
#pragma unroll
            for (int h = 0; h < 16; h++) { s += sS[h][tid]; q += sQ[h][tid]; }
            g_pS[blockIdx.x * 64 + tid] = s;
            g_pQ[blockIdx.x * 64 + tid] = q;
        }
    }
}

// ---- BN finalize: reduce GBLK partials per channel --------------------------
__global__ void __launch_bounds__(256)
k_bnfinal(const float* __restrict__ gamma, const float* __restrict__ beta, int n) {
    __shared__ float shS[8], shQ[8];
    int c = blockIdx.x;           // one channel per block
    int tid = threadIdx.x;
    float S = 0.f, Q = 0.f;
    for (int b = tid; b < GBLK; b += 256) {
        S += g_pS[b * 64 + c];
        Q += g_pQ[b * 64 + c];
    }
#pragma unroll
    for (int off = 16; off; off >>= 1) {
        S += __shfl_down_sync(0xffffffffu, S, off);
        Q += __shfl_down_sync(0xffffffffu, Q, off);
    }
    if ((tid & 31) == 0) { shS[tid >> 5] = S; shQ[tid >> 5] = Q; }
    __syncthreads();
    if (tid == 0) {
        float s = 0.f, q = 0.f;
#pragma unroll
        for (int w = 0; w < 8; w++) { s += shS[w]; q += shQ[w]; }
        float inv_n = 1.f / (float)n;
        float mean = s * inv_n;
        float var = fmaxf(q * inv_n - mean * mean, 0.f);
        float rstd = rsqrtf(var + BN_EPS);
        float a = gamma[c] * rstd;
        g_bnA[c] = a;
        g_bnB[c] = beta[c] - mean * a;
    }
}

// ---------------------------------------------------------------------------
extern "C" void kernel_launch(void* const* d_in, const int* in_sizes, int n_in,
                              void* d_out, int out_size) {
    const float* x = (const float*)d_in[0];
    const void* ei = d_in[1];
    int n = in_sizes[0] / 64;
    int E = in_sizes[1] / 2;
    if (n > NMAX || E > EMAX) return;

    int base = 2;
    if (n_in >= 13 && in_sizes[2] == 1) base = 3;   // skip batch_size scalar
    const float* W1  = (const float*)d_in[base + 0];
    const float* b1  = (const float*)d_in[base + 1];
    const float* ga1 = (const float*)d_in[base + 2];
    const float* be1 = (const float*)d_in[base + 3];
    const float* W2  = (const float*)d_in[base + 4];
    const float* b2  = (const float*)d_in[base + 5];
    const float* ga2 = (const float*)d_in[base + 6];
    const float* be2 = (const float*)d_in[base + 7];
    const float* W3  = (const float*)d_in[base + 8];
    const float* b3  = (const float*)d_in[base + 9];

    float *bufA = nullptr, *bufB = nullptr;
    cudaGetSymbolAddress((void**)&bufA, g_bufA);
    cudaGetSymbolAddress((void**)&bufB, g_bufB);
    cudaFuncSetAttribute(k_gemm, cudaFuncAttributeMaxDynamicSharedMemorySize,
                         GEMM_SMEM);

    int nb = (n + SCAN_ITEMS - 1) / SCAN_ITEMS;
    int eblk = (E + 255) / 256;
    int gemmblk = (n + 127) / 128;

    // --- preprocessing (4 launches) ---
    k_init<<<128, 256>>>((const unsigned int*)ei, E, n);
    k_hist<<<eblk, 256>>>(ei, E);
    k_scan<<<nb, 256>>>(n, nb);
    k_fill<<<eblk, 256>>>(ei, E);

    // --- layer 1 ---
    k_gemm<<<gemmblk, 128, GEMM_SMEM>>>(x, W1, 0, bufA, n);
    k_gather<<<GBLK, 256>>>((const float4*)bufA, b1, (float4*)bufB, n, 1);
    k_bnfinal<<<64, 256>>>(ga1, be1, n);

    // --- layer 2 ---
    k_gemm<<<gemmblk, 128, GEMM_SMEM>>>(bufB, W2, 1, bufA, n);
    k_gather<<<GBLK, 256>>>((const float4*)bufA, b2, (float4*)bufB, n, 1);
    k_bnfinal<<<64, 256>>>(ga2, be2, n);

    // --- layer 3 (final output) ---
    k_gemm<<<gemmblk, 128, GEMM_SMEM>>>(bufB, W3, 1, bufA, n);
    k_gather<<<GBLK, 256>>>((const float4*)bufA, b3, (float4*)d_out, n, 0);
}

// round 15
// speedup vs baseline: 1.5159x; 1.5159x over previous
#include <cuda_runtime.h>

// ---------------------------------------------------------------------------
// GCN 3-layer: (GCNConv -> BN -> ReLU) x2 -> GCNConv.  N=100k, E=1.2M, D=64.
//
// R14: - gather: ONE node per full warp (uniform loop), lanes cover
//        2 edges x 16 channel-quads (float4), unroll x2 -> 4 edges in flight,
//        shfl_xor(16) fold. Fixes R11 half-warp divergence regression.
//      - preprocessing: no init zero pass (fill re-zeroes g_cnt for next call,
//        scan seeds g_cursor=rowoff, detect zeroes lookback flags);
//        hist/fill do 4 edges/thread (atomic MLP=4).
//      - GEMM: 8x8 FFMA2 tile with dinv row-scale epilogue (unchanged).
//      - BN stats fused in gather (1480-block partials), tiny finalize.
// ---------------------------------------------------------------------------

#define NMAX 100000
#define EMAX 1200000
#define BN_EPS 1e-5f
#define GBLK 1480          // gather grid (10 blocks/SM), also #stat partials
#define SCAN_ITEMS 2048
#define GEMM_SMEM ((128 * 65 + 64 * 64) * 4)

__device__ float g_bufA[NMAX * 64];
__device__ float g_bufB[NMAX * 64];
__device__ int   g_cnt[NMAX];          // zero-init; fill re-zeroes each call
__device__ int   g_cursor[NMAX];
__device__ int   g_rowoff[NMAX + 1];
__device__ float g_dinv[NMAX];
__device__ int   g_csr[EMAX];
__device__ int   g_bagg[64];
__device__ int   g_bpref[64];
__device__ volatile int g_bflag[64];   // 0 none, 1 aggregate, 2 prefix
__device__ float g_pS[GBLK * 64];
__device__ float g_pQ[GBLK * 64];
__device__ float g_bnA[64];
__device__ float g_bnB[64];
__device__ int   g_is64;

// ---- packed fp32x2 FFMA2 (bit-exact vs 2x FFMA) -----------------------------
__device__ __forceinline__ unsigned long long pack2(float lo, float hi) {
    unsigned long long r;
    asm("mov.b64 %0, {%1, %2};" : "=l"(r) : "f"(lo), "f"(hi));
    return r;
}
__device__ __forceinline__ void unpack2(unsigned long long v, float& lo, float& hi) {
    asm("mov.b64 {%0, %1}, %2;" : "=f"(lo), "=f"(hi) : "l"(v));
}
__device__ __forceinline__ unsigned long long fma2(unsigned long long a,
                                                   unsigned long long b,
                                                   unsigned long long c) {
    unsigned long long d;
    asm("fma.rn.f32x2 %0, %1, %2, %3;" : "=l"(d) : "l"(a), "l"(b), "l"(c));
    return d;
}

__device__ __forceinline__ int edge_val(const void* ei, long long idx) {
    if (g_is64) return (int)((const long long*)ei)[idx];
    return ((const int*)ei)[idx];
}

// ---- detect int64-vs-int32 edge layout + zero lookback flags ----------------
__global__ void k_detect(const unsigned int* p, int E) {
    __shared__ int any;
    if (threadIdx.x == 0) any = 0;
    if (threadIdx.x < 64) g_bflag[threadIdx.x] = 0;
    __syncthreads();
    int samples = E < 4096 ? E : 4096;
    for (int i = threadIdx.x; i < samples; i += blockDim.x)
        if (p[2 * i + 1] != 0u) any = 1;   // nonzero hi-word => int32 layout
    __syncthreads();
    if (threadIdx.x == 0) g_is64 = any ? 0 : 1;
}

// ---- histogram: 4 edges/thread (atomic MLP=4) -------------------------------
__global__ void __launch_bounds__(256) k_hist(const void* ei, int E) {
    int e0 = (blockIdx.x * blockDim.x + threadIdx.x) * 4;
    if (e0 >= E) return;
    int d[4];
#pragma unroll
    for (int i = 0; i < 4; i++)
        if (e0 + i < E) d[i] = edge_val(ei, (long long)E + e0 + i);
#pragma unroll
    for (int i = 0; i < 4; i++)
        if (e0 + i < E) atomicAdd(&g_cnt[d[i]], 1);
}

// ---- single-kernel exclusive scan (decoupled lookback) + dinv + cursor ------
__global__ void __launch_bounds__(256) k_scan(int n, int nb) {
    __shared__ int wsum[8], woff[8];
    __shared__ int s_excl;
    int tid = threadIdx.x, b = blockIdx.x;
    int base = b * SCAN_ITEMS + tid * 8;
    int v[8];
    int tsum = 0;
#pragma unroll
    for (int i = 0; i < 8; i++) {
        v[i] = (base + i < n) ? g_cnt[base + i] : 0;
        tsum += v[i];
    }
    int lane = tid & 31, wid = tid >> 5;
    int inc = tsum;
#pragma unroll
    for (int off = 1; off < 32; off <<= 1) {
        int t = __shfl_up_sync(0xffffffffu, inc, off);
        if (lane >= off) inc += t;
    }
    if (lane == 31) wsum[wid] = inc;
    __syncthreads();
    if (tid == 0) {
        int acc = 0;
#pragma unroll
        for (int w = 0; w < 8; w++) { woff[w] = acc; acc += wsum[w]; }
        int excl = 0;
        if (b == 0) {
            *(volatile int*)&g_bpref[0] = acc;
            __threadfence();
            g_bflag[0] = 2;
        } else {
            *(volatile int*)&g_bagg[b] = acc;
            __threadfence();
            g_bflag[b] = 1;
            int p = b - 1;
            while (true) {
                int f;
                do { f = g_bflag[p]; } while (f == 0);
                __threadfence();
                if (f == 2) { excl += *(volatile int*)&g_bpref[p]; break; }
                excl += *(volatile int*)&g_bagg[p];
                p--;
            }
            *(volatile int*)&g_bpref[b] = excl + acc;
            __threadfence();
            g_bflag[b] = 2;
        }
        s_excl = excl;
        if (b == nb - 1) g_rowoff[n] = excl + acc;
    }
    __syncthreads();
    int run = s_excl + woff[wid] + (inc - tsum);
#pragma unroll
    for (int i = 0; i < 8; i++) {
        int idx = base + i;
        if (idx < n) {
            g_rowoff[idx] = run;
            g_cursor[idx] = run;                     // fill's atomic base
            g_dinv[idx] = rsqrtf((float)(v[i] + 1));
        }
        run += v[i];
    }
}

// ---- CSR fill: 4 edges/thread; also re-zeroes g_cnt for the next call ------
__global__ void __launch_bounds__(256) k_fill(const void* ei, int E, int n) {
    int gid = blockIdx.x * blockDim.x + threadIdx.x;
    int e0 = gid * 4;
    if (e0 < E) {
        int s[4], d[4];
#pragma unroll
        for (int i = 0; i < 4; i++)
            if (e0 + i < E) {
                s[i] = edge_val(ei, e0 + i);
                d[i] = edge_val(ei, (long long)E + e0 + i);
            }
#pragma unroll
        for (int i = 0; i < 4; i++)
            if (e0 + i < E) {
                int pos = atomicAdd(&g_cursor[d[i]], 1);
                g_csr[pos] = s[i];
            }
    }
    int total = gridDim.x * blockDim.x;
    for (int i = gid; i < n; i += total) g_cnt[i] = 0;
}

// ---- fused (BN+ReLU) + GEMM + dinv row-scale --------------------------------
// Hs[r,:] = dinv[r] * ( act(X[r,:]) @ W ).  128 rows/block, 8r x 8c per thread.
__global__ void __launch_bounds__(128)
k_gemm(const float* __restrict__ X, const float* __restrict__ W,
       int use_bn, float* __restrict__ H, int n) {
    extern __shared__ float sm[];
    float (*Xs)[65] = (float(*)[65])sm;   // 128 x 65
    float* Ws = sm + 128 * 65;            // 64 x 64

    int tid = threadIdx.x;
    int rowBase = blockIdx.x * 128;

    for (int i = tid; i < 64 * 64; i += 128) Ws[i] = W[i];
    for (int i = tid; i < 128 * 64; i += 128) {
        int r = i >> 6, c = i & 63;
        int gr = rowBase + r;
        float v = 0.f;
        if (gr < n) {
            v = X[gr * 64 + c];
            if (use_bn) v = fmaxf(fmaf(v, g_bnA[c], g_bnB[c]), 0.f);
        }
        Xs[r][c] = v;
    }
    __syncthreads();

    int rgrp = tid >> 3;          // 16 groups of 8 rows
    int cq = tid & 7;             // 8 col-groups of 8
    int r0 = rgrp * 8;

    unsigned long long acc[8][4];
#pragma unroll
    for (int i = 0; i < 8; i++)
#pragma unroll
        for (int j = 0; j < 4; j++) acc[i][j] = 0ULL;

#pragma unroll 4
    for (int k = 0; k < 64; k++) {
        unsigned long long xx[8];
#pragma unroll
        for (int i = 0; i < 8; i++) {
            float xv = Xs[r0 + i][k];
            xx[i] = pack2(xv, xv);
        }
        const float4* Wrow = (const float4*)(Ws + k * 64);
        float4 wa = Wrow[cq * 2 + 0];
        float4 wb = Wrow[cq * 2 + 1];
        unsigned long long wv[4] = {pack2(wa.x, wa.y), pack2(wa.z, wa.w),
                                    pack2(wb.x, wb.y), pack2(wb.z, wb.w)};
#pragma unroll
        for (int i = 0; i < 8; i++)
#pragma unroll
            for (int j = 0; j < 4; j++)
                acc[i][j] = fma2(xx[i], wv[j], acc[i][j]);
    }

#pragma unroll
    for (int i = 0; i < 8; i++) {
        int gr = rowBase + r0 + i;
        if (gr < n) {
            float dv = g_dinv[gr];
            float a0, a1, a2, a3, a4, a5, a6, a7;
            unpack2(acc[i][0], a0, a1);
            unpack2(acc[i][1], a2, a3);
            unpack2(acc[i][2], a4, a5);
            unpack2(acc[i][3], a6, a7);
            float4* dst = (float4*)(H + gr * 64 + cq * 8);
            dst[0] = make_float4(a0 * dv, a1 * dv, a2 * dv, a3 * dv);
            dst[1] = make_float4(a4 * dv, a5 * dv, a6 * dv, a7 * dv);
        }
    }
}

// ---- aggregation: ONE node per warp; lanes = 2 edges x 16 float4 quads ------
// out[n,:] = b + dinv[n]*( sum_{e:dst=n} Hs[src] + Hs[n] ),  Hs pre-scaled.
__device__ __forceinline__ float4 f4add(float4 a, float4 b) {
    return make_float4(a.x + b.x, a.y + b.y, a.z + b.z, a.w + b.w);
}

__global__ void __launch_bounds__(256)
k_gather(const float4* __restrict__ Hs, const float* __restrict__ bias,
         float4* __restrict__ out, int n, int do_stats) {
    __shared__ float sS[8][64];
    __shared__ float sQ[8][64];
    int tid = threadIdx.x;
    int lane = tid & 31;
    int warp = tid >> 5;               // 8 warps/block
    int c = lane & 15;                 // channel quad
    int epick = lane >> 4;             // 0 or 1: which edge of the pair
    int gwarp = blockIdx.x * 8 + warp;
    int nwarps = gridDim.x * 8;

    float4 S = make_float4(0.f, 0.f, 0.f, 0.f);
    float4 Q = make_float4(0.f, 0.f, 0.f, 0.f);
    float4 b4 = ((const float4*)bias)[c];

    for (int node = gwarp; node < n; node += nwarps) {
        int beg = g_rowoff[node];
        int end = g_rowoff[node + 1];
        float dn = g_dinv[node];

        float4 a0 = make_float4(0.f, 0.f, 0.f, 0.f);
        float4 a1 = make_float4(0.f, 0.f, 0.f, 0.f);
        int j = beg;
        // 4 edges per iteration: lanes split into 2 edge slots, 2 batches.
        for (; j + 4 <= end; j += 4) {
            int s0 = g_csr[j + epick];
            int s1 = g_csr[j + 2 + epick];
            float4 v0 = Hs[(long long)s0 * 16 + c];
            float4 v1 = Hs[(long long)s1 * 16 + c];
            a0 = f4add(a0, v0);
            a1 = f4add(a1, v1);
        }
        if (j + 2 <= end) {
            int s0 = g_csr[j + epick];
            a0 = f4add(a0, Hs[(long long)s0 * 16 + c]);
            j += 2;
        }
        if (j < end && epick == 0) {   // odd tail: lower half only
            int s0 = g_csr[j];
            a1 = f4add(a1, Hs[(long long)s0 * 16 + c]);
        }
        float4 a = f4add(a0, a1);
        // fold upper-half edge partials into lower half
        a.x += __shfl_xor_sync(0xffffffffu, a.x, 16);
        a.y += __shfl_xor_sync(0xffffffffu, a.y, 16);
        a.z += __shfl_xor_sync(0xffffffffu, a.z, 16);
        a.w += __shfl_xor_sync(0xffffffffu, a.w, 16);

        if (epick == 0) {
            float4 self = Hs[(long long)node * 16 + c];
            float4 t = f4add(a, self);
            float4 o = make_float4(fmaf(dn, t.x, b4.x), fmaf(dn, t.y, b4.y),
                                   fmaf(dn, t.z, b4.z), fmaf(dn, t.w, b4.w));
            out[(long long)node * 16 + c] = o;
            if (do_stats) {
                S = f4add(S, o);
                Q.x = fmaf(o.x, o.x, Q.x); Q.y = fmaf(o.y, o.y, Q.y);
                Q.z = fmaf(o.z, o.z, Q.z); Q.w = fmaf(o.w, o.w, Q.w);
            }
        }
    }

    if (do_stats) {
        if (epick == 0) {
            ((float4*)&sS[warp][c * 4])[0] = S;
            ((float4*)&sQ[warp][c * 4])[0] = Q;
        }
        __syncthreads();
        if (tid < 64) {
            float s = 0.f, q = 0.f;
#pragma unroll
            for (int h = 0; h < 8; h++) { s += sS[h][tid]; q += sQ[h][tid]; }
            g_pS[blockIdx.x * 64 + tid] = s;
            g_pQ[blockIdx.x * 64 + tid] = q;
        }
    }
}

// ---- BN finalize: reduce GBLK partials per channel --------------------------
__global__ void __launch_bounds__(256)
k_bnfinal(const float* __restrict__ gamma, const float* __restrict__ beta, int n) {
    __shared__ float shS[8], shQ[8];
    int c = blockIdx.x;           // one channel per block
    int tid = threadIdx.x;
    float S = 0.f, Q = 0.f;
    for (int b = tid; b < GBLK; b += 256) {
        S += g_pS[b * 64 + c];
        Q += g_pQ[b * 64 + c];
    }
#pragma unroll
    for (int off = 16; off; off >>= 1) {
        S += __shfl_down_sync(0xffffffffu, S, off);
        Q += __shfl_down_sync(0xffffffffu, Q, off);
    }
    if ((tid & 31) == 0) { shS[tid >> 5] = S; shQ[tid >> 5] = Q; }
    __syncthreads();
    if (tid == 0) {
        float s = 0.f, q = 0.f;
#pragma unroll
        for (int w = 0; w < 8; w++) { s += shS[w]; q += shQ[w]; }
        float inv_n = 1.f / (float)n;
        float mean = s * inv_n;
        float var = fmaxf(q * inv_n - mean * mean, 0.f);
        float rstd = rsqrtf(var + BN_EPS);
        float a = gamma[c] * rstd;
        g_bnA[c] = a;
        g_bnB[c] = beta[c] - mean * a;
    }
}

// ---------------------------------------------------------------------------
extern "C" void kernel_launch(void* const* d_in, const int* in_sizes, int n_in,
                              void* d_out, int out_size) {
    const float* x = (const float*)d_in[0];
    const void* ei = d_in[1];
    int n = in_sizes[0] / 64;
    int E = in_sizes[1] / 2;
    if (n > NMAX || E > EMAX) return;

    int base = 2;
    if (n_in >= 13 && in_sizes[2] == 1) base = 3;   // skip batch_size scalar
    const float* W1  = (const float*)d_in[base + 0];
    const float* b1  = (const float*)d_in[base + 1];
    const float* ga1 = (const float*)d_in[base + 2];
    const float* be1 = (const float*)d_in[base + 3];
    const float* W2  = (const float*)d_in[base + 4];
    const float* b2  = (const float*)d_in[base + 5];
    const float* ga2 = (const float*)d_in[base + 6];
    const float* be2 = (const float*)d_in[base + 7];
    const float* W3  = (const float*)d_in[base + 8];
    const float* b3  = (const float*)d_in[base + 9];

    float *bufA = nullptr, *bufB = nullptr;
    cudaGetSymbolAddress((void**)&bufA, g_bufA);
    cudaGetSymbolAddress((void**)&bufB, g_bufB);
    cudaFuncSetAttribute(k_gemm, cudaFuncAttributeMaxDynamicSharedMemorySize,
                         GEMM_SMEM);

    int nb = (n + SCAN_ITEMS - 1) / SCAN_ITEMS;
    int e4blk = (E + 1023) / 1024;           // 4 edges/thread, 256 thr
    int gemmblk = (n + 127) / 128;

    // --- preprocessing (4 launches; g_cnt starts zero: static init on call 1,
    //     re-zeroed by k_fill on every call thereafter) ---
    k_detect<<<1, 256>>>((const unsigned int*)ei, E);
    k_hist<<<e4blk, 256>>>(ei, E);
    k_scan<<<nb, 256>>>(n, nb);
    k_fill<<<e4blk, 256>>>(ei, E, n);

    // --- layer 1 ---
    k_gemm<<<gemmblk, 128, GEMM_SMEM>>>(x, W1, 0, bufA, n);
    k_gather<<<GBLK, 256>>>((const float4*)bufA, b1, (float4*)bufB, n, 1);
    k_bnfinal<<<64, 256>>>(ga1, be1, n);

    // --- layer 2 ---
    k_gemm<<<gemmblk, 128, GEMM_SMEM>>>(bufB, W2, 1, bufA, n);
    k_gather<<<GBLK, 256>>>((const float4*)bufA, b2, (float4*)bufB, n, 1);
    k_bnfinal<<<64, 256>>>(ga2, be2, n);

    // --- layer 3 (final output) ---
    k_gemm<<<gemmblk, 128, GEMM_SMEM>>>(bufB, W3, 1, bufA, n);
    k_gather<<<GBLK, 256>>>((const float4*)bufA, b3, (float4*)d_out, n, 0);
}